// round 1
// baseline (speedup 1.0000x reference)
#include <cuda_runtime.h>
#include <cstdint>

#define BATCH   8
#define VN      201
#define DIM     256
#define PAIRS   20301          /* VN*(VN+1)/2 */
#define MROWS   162408         /* BATCH*PAIRS  */
#define TILESM  1269           /* ceil(MROWS/128) */
#define KSEL    100
#define LSLOPE  0.01f
#define CNT     323208.0       /* BATCH*VN*VN */

// ---------------- device scratch (no cudaMalloc allowed) ----------------
__device__ float g_bufA[MROWS * 256];
__device__ float g_bufB[MROWS * 256];
__device__ int2  g_vw[PAIRS];
__device__ float g_wpair[PAIRS];
__device__ float g_psum[TILESM * 256];
__device__ float g_psq [TILESM * 256];
__device__ float g_sArr[1024];
__device__ float g_tArr[1024];
__device__ float g_logits[BATCH * VN * VN];

// ---------------- f32x2 packed-FMA helpers ----------------
__device__ __forceinline__ unsigned long long pk2(float a) {
    unsigned long long r; unsigned int u = __float_as_uint(a);
    asm("mov.b64 %0, {%1, %1};" : "=l"(r) : "r"(u));
    return r;
}
__device__ __forceinline__ void fma2(unsigned long long& d, unsigned long long a, unsigned long long b) {
    asm("fma.rn.f32x2 %0, %1, %2, %0;" : "+l"(d) : "l"(a), "l"(b));
}
__device__ __forceinline__ void unpk2(unsigned long long v, float& lo, float& hi) {
    unsigned int l, h;
    asm("mov.b64 {%0, %1}, %2;" : "=r"(l), "=r"(h) : "l"(v));
    lo = __uint_as_float(l); hi = __uint_as_float(h);
}

// ---------------- init: pair -> (v,w) LUT + BN weights ----------------
__global__ void init_lut() {
    int t = threadIdx.x;
    for (int v = t; v < VN; v += blockDim.x) {
        int base = v * VN - (v * (v - 1)) / 2;
        for (int w = v; w < VN; w++) {
            int p = base + (w - v);
            g_vw[p] = make_int2(v, w);
            g_wpair[p] = (v == w) ? 1.0f : 2.0f;
        }
    }
}

// ---------------- pairwise |x_v - x_w| into packed half-matrix ----------------
__global__ void absdiff_kernel(const float* __restrict__ x) {
    int idx = blockIdx.x * blockDim.x + threadIdx.x;
    if (idx >= MROWS * 64) return;
    int r  = idx >> 6;
    int cq = idx & 63;
    int b = r / PAIRS, p = r - b * PAIRS;
    int2 vw = g_vw[p];
    const float4 xv = *(const float4*)&x[(size_t)(b * VN + vw.x) * 256 + cq * 4];
    const float4 xw = *(const float4*)&x[(size_t)(b * VN + vw.y) * 256 + cq * 4];
    float4 o;
    o.x = fabsf(xv.x - xw.x); o.y = fabsf(xv.y - xw.y);
    o.z = fabsf(xv.z - xw.z); o.w = fabsf(xv.w - xw.w);
    *(float4*)&g_bufA[(size_t)r * 256 + cq * 4] = o;
}

// ---------------- fused GEMM: C = act(affine(A)) @ W^T + bias, + BN partial stats ----------------
// A row-major [MROWS, K], W row-major [Ntot, K], C row-major [MROWS, ldc].
template<bool AFFINE, bool SWAP>
__global__ __launch_bounds__(256, 2)
void gemm_bn(int K, int ldc, int affOff,
             const float* __restrict__ W, const float* __restrict__ bias)
{
    const float* A  = SWAP ? g_bufB : g_bufA;
    float*       C  = SWAP ? g_bufA : g_bufB;

    __shared__ float As[16][132];
    __shared__ float Bs[16][132];

    const int t = threadIdx.x;
    const int tm = blockIdx.x, tn = blockIdx.y;
    const int rowBase = tm * 128, colBase = tn * 128;
    const int ar = t >> 2;                 // 0..63
    const int ac = (t & 3) << 2;           // 0,4,8,12

    unsigned long long acc[8][4];
#pragma unroll
    for (int i = 0; i < 8; i++)
#pragma unroll
        for (int j = 0; j < 4; j++) acc[i][j] = 0ull;

    const bool v0 = (rowBase + ar)      < MROWS;
    const bool v1 = (rowBase + ar + 64) < MROWS;
    const float* Ag0 = A + (size_t)(rowBase + ar) * K + ac;
    const float* Ag1 = A + (size_t)(rowBase + ar + 64) * K + ac;
    const float* Wg0 = W + (size_t)(colBase + ar) * K + ac;
    const float* Wg1 = W + (size_t)(colBase + ar + 64) * K + ac;

    const int ty = t >> 4, tx = t & 15;

    for (int kc = 0; kc < K; kc += 16) {
        float4 a0 = make_float4(0.f, 0.f, 0.f, 0.f), a1 = a0;
        if (v0) a0 = *(const float4*)(Ag0 + kc);
        if (v1) a1 = *(const float4*)(Ag1 + kc);
        float4 b0 = *(const float4*)(Wg0 + kc);
        float4 b1 = *(const float4*)(Wg1 + kc);

        if (AFFINE) {
            float4 s4 = *(const float4*)&g_sArr[affOff + kc + ac];
            float4 t4 = *(const float4*)&g_tArr[affOff + kc + ac];
            a0.x = a0.x * s4.x + t4.x; a0.x = a0.x >= 0.f ? a0.x : LSLOPE * a0.x;
            a0.y = a0.y * s4.y + t4.y; a0.y = a0.y >= 0.f ? a0.y : LSLOPE * a0.y;
            a0.z = a0.z * s4.z + t4.z; a0.z = a0.z >= 0.f ? a0.z : LSLOPE * a0.z;
            a0.w = a0.w * s4.w + t4.w; a0.w = a0.w >= 0.f ? a0.w : LSLOPE * a0.w;
            a1.x = a1.x * s4.x + t4.x; a1.x = a1.x >= 0.f ? a1.x : LSLOPE * a1.x;
            a1.y = a1.y * s4.y + t4.y; a1.y = a1.y >= 0.f ? a1.y : LSLOPE * a1.y;
            a1.z = a1.z * s4.z + t4.z; a1.z = a1.z >= 0.f ? a1.z : LSLOPE * a1.z;
            a1.w = a1.w * s4.w + t4.w; a1.w = a1.w >= 0.f ? a1.w : LSLOPE * a1.w;
        }

        As[ac + 0][ar] = a0.x; As[ac + 1][ar] = a0.y; As[ac + 2][ar] = a0.z; As[ac + 3][ar] = a0.w;
        As[ac + 0][ar + 64] = a1.x; As[ac + 1][ar + 64] = a1.y; As[ac + 2][ar + 64] = a1.z; As[ac + 3][ar + 64] = a1.w;
        Bs[ac + 0][ar] = b0.x; Bs[ac + 1][ar] = b0.y; Bs[ac + 2][ar] = b0.z; Bs[ac + 3][ar] = b0.w;
        Bs[ac + 0][ar + 64] = b1.x; Bs[ac + 1][ar + 64] = b1.y; Bs[ac + 2][ar + 64] = b1.z; Bs[ac + 3][ar + 64] = b1.w;
        __syncthreads();

#pragma unroll
        for (int k = 0; k < 16; k++) {
            float4 av0 = *(const float4*)&As[k][ty * 8];
            float4 av1 = *(const float4*)&As[k][ty * 8 + 4];
            ulonglong2 bv0 = *(const ulonglong2*)&Bs[k][tx * 8];
            ulonglong2 bv1 = *(const ulonglong2*)&Bs[k][tx * 8 + 4];
            unsigned long long bb[4] = { bv0.x, bv0.y, bv1.x, bv1.y };
            float aa[8] = { av0.x, av0.y, av0.z, av0.w, av1.x, av1.y, av1.z, av1.w };
#pragma unroll
            for (int i = 0; i < 8; i++) {
                unsigned long long ap = pk2(aa[i]);
#pragma unroll
                for (int j = 0; j < 4; j++) fma2(acc[i][j], ap, bb[j]);
            }
        }
        __syncthreads();
    }

    // ---------- epilogue: bias add, store, weighted per-channel partial sums ----------
    float4 bb0 = *(const float4*)&bias[colBase + tx * 8];
    float4 bb1 = *(const float4*)&bias[colBase + tx * 8 + 4];
    float psumL[8] = {0,0,0,0,0,0,0,0};
    float psqL [8] = {0,0,0,0,0,0,0,0};

#pragma unroll
    for (int i = 0; i < 8; i++) {
        int gr = rowBase + ty * 8 + i;
        bool ok = gr < MROWS;
        float wt = ok ? g_wpair[gr % PAIRS] : 0.f;
        float y[8];
#pragma unroll
        for (int j = 0; j < 4; j++) unpk2(acc[i][j], y[2 * j], y[2 * j + 1]);
        y[0] += bb0.x; y[1] += bb0.y; y[2] += bb0.z; y[3] += bb0.w;
        y[4] += bb1.x; y[5] += bb1.y; y[6] += bb1.z; y[7] += bb1.w;
        if (ok) {
            float4 o0 = make_float4(y[0], y[1], y[2], y[3]);
            float4 o1 = make_float4(y[4], y[5], y[6], y[7]);
            *(float4*)&C[(size_t)gr * ldc + colBase + tx * 8]     = o0;
            *(float4*)&C[(size_t)gr * ldc + colBase + tx * 8 + 4] = o1;
        }
#pragma unroll
        for (int j = 0; j < 8; j++) { psumL[j] += wt * y[j]; psqL[j] += wt * y[j] * y[j]; }
    }

    // deterministic reduction over the 16 ty groups via smem
    float* sred = &As[0][0];   // 2112 floats >= 2048
    __syncthreads();
#pragma unroll
    for (int j = 0; j < 8; j++) sred[ty * 128 + tx * 8 + j] = psumL[j];
    __syncthreads();
    if (t < 128) {
        float s = 0.f;
#pragma unroll
        for (int i = 0; i < 16; i++) s += sred[i * 128 + t];
        g_psum[(size_t)tm * ldc + colBase + t] = s;
    }
    __syncthreads();
#pragma unroll
    for (int j = 0; j < 8; j++) sred[ty * 128 + tx * 8 + j] = psqL[j];
    __syncthreads();
    if (t < 128) {
        float s = 0.f;
#pragma unroll
        for (int i = 0; i < 16; i++) s += sred[i * 128 + t];
        g_psq[(size_t)tm * ldc + colBase + t] = s;
    }
}

// ---------------- reduce partials -> BN affine (s,t) per channel ----------------
__global__ void stats_kernel(int outOff, int Ntot,
                             const float* __restrict__ gamma, const float* __restrict__ beta)
{
    int c = blockIdx.x;
    int t = threadIdx.x;
    double s = 0.0, q = 0.0;
    for (int i = t; i < TILESM; i += 256) {
        s += (double)g_psum[(size_t)i * Ntot + c];
        q += (double)g_psq [(size_t)i * Ntot + c];
    }
    __shared__ double rs[256], rq[256];
    rs[t] = s; rq[t] = q;
    __syncthreads();
    for (int st = 128; st > 0; st >>= 1) {
        if (t < st) { rs[t] += rs[t + st]; rq[t] += rq[t + st]; }
        __syncthreads();
    }
    if (t == 0) {
        double mean = rs[0] / CNT;
        double var  = rq[0] / CNT - mean * mean;
        float inv = rsqrtf((float)var + 1e-5f);
        float sc  = gamma[c] * inv;
        g_sArr[outOff + c] = sc;
        g_tArr[outOff + c] = beta[c] - (float)mean * sc;
    }
}

// ---------------- final linear -> symmetric logit scatter ----------------
__global__ void logits_kernel(const float* __restrict__ w4, const float* __restrict__ b4)
{
    int warp = threadIdx.x >> 5, lane = threadIdx.x & 31;
    int r = blockIdx.x * 8 + warp;
    if (r >= MROWS) return;
    int c = lane * 4;
    float4 v  = *(const float4*)&g_bufA[(size_t)r * 128 + c];
    float4 s4 = *(const float4*)&g_sArr[768 + c];
    float4 t4 = *(const float4*)&g_tArr[768 + c];
    float4 w  = *(const float4*)&w4[c];
    float a, sum = 0.f;
    a = v.x * s4.x + t4.x; a = a >= 0.f ? a : LSLOPE * a; sum += a * w.x;
    a = v.y * s4.y + t4.y; a = a >= 0.f ? a : LSLOPE * a; sum += a * w.y;
    a = v.z * s4.z + t4.z; a = a >= 0.f ? a : LSLOPE * a; sum += a * w.z;
    a = v.w * s4.w + t4.w; a = a >= 0.f ? a : LSLOPE * a; sum += a * w.w;
#pragma unroll
    for (int off = 16; off > 0; off >>= 1) sum += __shfl_down_sync(0xffffffffu, sum, off);
    if (lane == 0) {
        float lg = sum + b4[0];
        int b = r / PAIRS, p = r - b * PAIRS;
        int2 vw = g_vw[p];
        g_logits[((size_t)b * VN + vw.x) * VN + vw.y] = lg;
        g_logits[((size_t)b * VN + vw.y) * VN + vw.x] = lg;
    }
}

// ---------------- row softmax + top-K mask ----------------
__global__ void softmax_topk(float* __restrict__ out)
{
    int bv = blockIdx.x;
    int b = bv / VN, v = bv % VN;
    int t = threadIdx.x;
    __shared__ float sl[204];
    __shared__ float red[256];

    float lv = -3.402823466e38f;
    if (t < VN) { lv = g_logits[((size_t)b * VN + v) * VN + t]; sl[t] = lv; }
    red[t] = lv;
    __syncthreads();
    for (int s = 128; s > 0; s >>= 1) {
        if (t < s) red[t] = fmaxf(red[t], red[t + s]);
        __syncthreads();
    }
    float mx = red[0];
    __syncthreads();
    float e = (t < VN) ? __expf(lv - mx) : 0.f;
    red[t] = e;
    __syncthreads();
    for (int s = 128; s > 0; s >>= 1) {
        if (t < s) red[t] += red[t + s];
        __syncthreads();
    }
    float inv = 1.f / red[0];
    if (t < VN) {
        int cnt = 0;
        for (int j = 0; j < VN; j++) {
            float lj = sl[j];
            cnt += (lj > lv) || (lj == lv && j < t);
        }
        out[((size_t)b * VN + v) * VN + t] = (cnt < KSEL) ? e * inv : 0.f;
    }
}

// ---------------- launch ----------------
extern "C" void kernel_launch(void* const* d_in, const int* in_sizes, int n_in,
                              void* d_out, int out_size)
{
    (void)in_sizes; (void)n_in; (void)out_size;
    const float* x   = (const float*)d_in[0];
    const float* w0  = (const float*)d_in[1];
    const float* b0  = (const float*)d_in[2];
    const float* g0  = (const float*)d_in[3];
    const float* be0 = (const float*)d_in[4];
    const float* w1  = (const float*)d_in[5];
    const float* b1  = (const float*)d_in[6];
    const float* g1  = (const float*)d_in[7];
    const float* be1 = (const float*)d_in[8];
    const float* w2  = (const float*)d_in[9];
    const float* b2  = (const float*)d_in[10];
    const float* g2  = (const float*)d_in[11];
    const float* be2 = (const float*)d_in[12];
    const float* w3  = (const float*)d_in[13];
    const float* b3  = (const float*)d_in[14];
    const float* g3  = (const float*)d_in[15];
    const float* be3 = (const float*)d_in[16];
    const float* w4  = (const float*)d_in[17];
    const float* b4  = (const float*)d_in[18];

    init_lut<<<1, 256>>>();
    absdiff_kernel<<<(MROWS * 64 + 255) / 256, 256>>>(x);

    // L0: bufA(absdiff, K=256) -> bufB (N=256)
    gemm_bn<false, false><<<dim3(TILESM, 2), 256>>>(256, 256, 0, w0, b0);
    stats_kernel<<<256, 256>>>(0, 256, g0, be0);

    // L1: bufB -> bufA (K=256, N=256), affine of layer0 stats
    gemm_bn<true, true><<<dim3(TILESM, 2), 256>>>(256, 256, 0, w1, b1);
    stats_kernel<<<256, 256>>>(256, 256, g1, be1);

    // L2: bufA -> bufB (K=256, N=128)
    gemm_bn<true, false><<<dim3(TILESM, 1), 256>>>(256, 128, 256, w2, b2);
    stats_kernel<<<128, 256>>>(512, 128, g2, be2);

    // L3: bufB -> bufA (K=128, N=128)
    gemm_bn<true, true><<<dim3(TILESM, 1), 256>>>(128, 128, 512, w3, b3);
    stats_kernel<<<128, 256>>>(768, 128, g3, be3);

    // L4: bufA -> symmetric logits
    logits_kernel<<<MROWS / 8, 256>>>(w4, b4);

    // softmax over axis-2 + top-K mask
    softmax_topk<<<BATCH * VN, 256>>>((float*)d_out);
}